// round 1
// baseline (speedup 1.0000x reference)
#include <cuda_runtime.h>
#include <math.h>

#define BATCH 65536
#define FEAT  1808

// Scratch (static device globals; no allocation in kernel_launch)
__device__ float g_feats[(size_t)BATCH * FEAT];   // [B, 1808]
__device__ float g_h1[(size_t)BATCH * 256];       // [B, 256]
__device__ float g_h2[(size_t)BATCH * 128];       // [B, 128]

// ---------------------------------------------------------------------------
// Kernel 1: features (x copy, gram_cols 32x32, gram_rows 16x16), warp/sample
// ---------------------------------------------------------------------------
__global__ __launch_bounds__(256) void feat_kernel(const float* __restrict__ x) {
    int gw = (blockIdx.x * blockDim.x + threadIdx.x) >> 5;  // sample id
    int lane = threadIdx.x & 31;
    if (gw >= BATCH) return;
    const float* xr = x + (size_t)gw * 512;
    float* fr = g_feats + (size_t)gw * FEAT;

    // lane holds column `lane` of P: c[k] = P[k][lane], coalesced loads
    float c[16];
#pragma unroll
    for (int k = 0; k < 16; k++) c[k] = xr[k * 32 + lane];

    // copy x into feats[0:512)
#pragma unroll
    for (int k = 0; k < 16; k++) fr[k * 32 + lane] = c[k];

    // gram_cols[i][j] = sum_k P[k][i]*P[k][j]; j = lane
#pragma unroll
    for (int i = 0; i < 32; i++) {
        float acc = 0.f;
#pragma unroll
        for (int k = 0; k < 16; k++)
            acc = fmaf(__shfl_sync(0xffffffffu, c[k], i), c[k], acc);
        fr[512 + i * 32 + lane] = acc;
    }

    // gram_rows[i][j] = sum_c P[i][c]*P[j][c] = warp-reduce over lanes of c[i]*c[j]
    float outv[8];
#pragma unroll
    for (int r = 0; r < 8; r++) outv[r] = 0.f;
#pragma unroll
    for (int i = 0; i < 16; i++) {
#pragma unroll
        for (int j = i; j < 16; j++) {
            float v = c[i] * c[j];
            v += __shfl_xor_sync(0xffffffffu, v, 16);
            v += __shfl_xor_sync(0xffffffffu, v, 8);
            v += __shfl_xor_sync(0xffffffffu, v, 4);
            v += __shfl_xor_sync(0xffffffffu, v, 2);
            v += __shfl_xor_sync(0xffffffffu, v, 1);
            int p1 = i * 16 + j;
            if (lane == (p1 & 31)) outv[p1 >> 5] = v;
            if (i != j) {
                int p2 = j * 16 + i;
                if (lane == (p2 & 31)) outv[p2 >> 5] = v;
            }
        }
    }
#pragma unroll
    for (int r = 0; r < 8; r++) fr[1536 + r * 32 + lane] = outv[r];
}

// ---------------------------------------------------------------------------
// Kernel 2: singular values via per-thread cyclic Jacobi on 16x16 Gram.
// Symmetric upper-triangular storage in 136 registers, all static indices.
// ---------------------------------------------------------------------------
__device__ __forceinline__ constexpr int SIDX(int i, int j) {
    // requires i <= j
    return i * 16 - i * (i - 1) / 2 + (j - i);
}

__global__ __launch_bounds__(128) void svd_kernel() {
    int s = blockIdx.x * blockDim.x + threadIdx.x;
    if (s >= BATCH) return;
    float* fr = g_feats + (size_t)s * FEAT;

    float a[136];
#pragma unroll
    for (int i = 0; i < 16; i++)
#pragma unroll
        for (int j = i; j < 16; j++)
            a[SIDX(i, j)] = fr[1536 + i * 16 + j];

    for (int sw = 0; sw < 7; sw++) {
#pragma unroll
        for (int p = 0; p < 15; p++) {
#pragma unroll
            for (int q = p + 1; q < 16; q++) {
                float apq = a[SIDX(p, q)];
                if (fabsf(apq) > 1e-12f) {
                    float app = a[SIDX(p, p)];
                    float aqq = a[SIDX(q, q)];
                    float theta = __fdividef(0.5f * (aqq - app), apq);
                    float t = copysignf(1.0f, theta) /
                              (fabsf(theta) + sqrtf(fmaf(theta, theta, 1.0f)));
                    float cth = rsqrtf(fmaf(t, t, 1.0f));
                    float sth = t * cth;
                    a[SIDX(p, p)] = app - t * apq;
                    a[SIDX(q, q)] = aqq + t * apq;
                    a[SIDX(p, q)] = 0.f;
#pragma unroll
                    for (int i = 0; i < 16; i++) {
                        if (i != p && i != q) {
                            float aip = (i < p) ? a[SIDX(i, p)] : a[SIDX(p, i)];
                            float aiq = (i < q) ? a[SIDX(i, q)] : a[SIDX(q, i)];
                            float n1 = cth * aip - sth * aiq;
                            float n2 = sth * aip + cth * aiq;
                            if (i < p) a[SIDX(i, p)] = n1; else a[SIDX(p, i)] = n1;
                            if (i < q) a[SIDX(i, q)] = n2; else a[SIDX(q, i)] = n2;
                        }
                    }
                }
            }
        }
    }

    float sv[16];
#pragma unroll
    for (int i = 0; i < 16; i++) sv[i] = sqrtf(fmaxf(a[SIDX(i, i)], 0.f));

    // sort descending: unrolled bubble network (static indices -> registers)
#pragma unroll
    for (int i = 0; i < 15; i++)
#pragma unroll
        for (int j = 0; j < 15 - i; j++) {
            float hi = fmaxf(sv[j], sv[j + 1]);
            float lo = fminf(sv[j], sv[j + 1]);
            sv[j] = hi;
            sv[j + 1] = lo;
        }
#pragma unroll
    for (int i = 0; i < 16; i++) fr[1792 + i] = sv[i];
}

// ---------------------------------------------------------------------------
// SGEMM: C[M,N] = relu?(A[M,K] @ B[K,N] + bias), 128x128 tile, 8x8/thread
// Requires: M%128==0, N%128==0, K%16==0
// ---------------------------------------------------------------------------
__global__ __launch_bounds__(256) void sgemm_bias_relu(
    int M, int N, int K,
    const float* __restrict__ A,
    const float* __restrict__ Bw,
    const float* __restrict__ bias,
    float* __restrict__ C,
    int do_relu)
{
    const int BK = 16;
    __shared__ float As[BK][128];
    __shared__ float Bs[BK][128];
    int tid = threadIdx.x;
    int bx = blockIdx.x, by = blockIdx.y;
    int tcol = tid & 15, trow = tid >> 4;

    float acc[8][8];
#pragma unroll
    for (int i = 0; i < 8; i++)
#pragma unroll
        for (int j = 0; j < 8; j++) acc[i][j] = 0.f;

    const float* Ab = A + (size_t)by * 128 * K;
    const float* Bb = Bw + bx * 128;

    int arow = tid >> 2, acol = (tid & 3) << 2;
    int brow = tid >> 5, bcol = (tid & 31) << 2;

    for (int k0 = 0; k0 < K; k0 += BK) {
        float4 av0 = *(const float4*)(Ab + (size_t)arow * K + k0 + acol);
        float4 av1 = *(const float4*)(Ab + (size_t)(arow + 64) * K + k0 + acol);
        As[acol + 0][arow] = av0.x; As[acol + 1][arow] = av0.y;
        As[acol + 2][arow] = av0.z; As[acol + 3][arow] = av0.w;
        As[acol + 0][arow + 64] = av1.x; As[acol + 1][arow + 64] = av1.y;
        As[acol + 2][arow + 64] = av1.z; As[acol + 3][arow + 64] = av1.w;

        float4 bv0 = *(const float4*)(Bb + (size_t)(k0 + brow) * N + bcol);
        float4 bv1 = *(const float4*)(Bb + (size_t)(k0 + brow + 8) * N + bcol);
        *(float4*)&Bs[brow][bcol] = bv0;
        *(float4*)&Bs[brow + 8][bcol] = bv1;
        __syncthreads();

#pragma unroll
        for (int k = 0; k < BK; k++) {
            float ra[8], rb[8];
            *(float4*)(ra)     = *(const float4*)&As[k][trow * 8];
            *(float4*)(ra + 4) = *(const float4*)&As[k][trow * 8 + 4];
            *(float4*)(rb)     = *(const float4*)&Bs[k][tcol * 8];
            *(float4*)(rb + 4) = *(const float4*)&Bs[k][tcol * 8 + 4];
#pragma unroll
            for (int i = 0; i < 8; i++)
#pragma unroll
                for (int j = 0; j < 8; j++)
                    acc[i][j] = fmaf(ra[i], rb[j], acc[i][j]);
        }
        __syncthreads();
    }

    // epilogue: bias + relu, float4 stores
#pragma unroll
    for (int i = 0; i < 8; i++) {
        size_t row = (size_t)by * 128 + trow * 8 + i;
#pragma unroll
        for (int jv = 0; jv < 2; jv++) {
            int col = bx * 128 + tcol * 8 + jv * 4;
            float4 v;
            v.x = acc[i][jv * 4 + 0] + bias[col + 0];
            v.y = acc[i][jv * 4 + 1] + bias[col + 1];
            v.z = acc[i][jv * 4 + 2] + bias[col + 2];
            v.w = acc[i][jv * 4 + 3] + bias[col + 3];
            if (do_relu) {
                v.x = fmaxf(v.x, 0.f); v.y = fmaxf(v.y, 0.f);
                v.z = fmaxf(v.z, 0.f); v.w = fmaxf(v.w, 0.f);
            }
            *(float4*)(C + row * N + col) = v;
        }
    }
}

// ---------------------------------------------------------------------------
// Kernel 4: fused layers 3+4: out = relu(h2 @ W3 + b3) @ W4 + b4
// ---------------------------------------------------------------------------
__global__ __launch_bounds__(256) void tail_kernel(
    const float* __restrict__ W3, const float* __restrict__ b3,
    const float* __restrict__ W4, const float* __restrict__ b4,
    float* __restrict__ out)
{
    __shared__ float sW3[128 * 64];
    __shared__ float sb3[64];
    __shared__ float sW4[64];
    int tid = threadIdx.x;
    for (int i = tid; i < 128 * 64; i += 256) sW3[i] = W3[i];
    if (tid < 64) { sb3[tid] = b3[tid]; sW4[tid] = W4[tid]; }
    __syncthreads();

    int s = blockIdx.x * 256 + tid;
    if (s >= BATCH) return;
    const float4* h2r = (const float4*)(g_h2 + (size_t)s * 128);

    float h3[64];
#pragma unroll
    for (int o = 0; o < 64; o++) h3[o] = sb3[o];

    for (int k4 = 0; k4 < 32; k4++) {
        float4 v = h2r[k4];
        float hv[4] = {v.x, v.y, v.z, v.w};
#pragma unroll
        for (int u = 0; u < 4; u++) {
            const float* wrow = &sW3[(k4 * 4 + u) * 64];
#pragma unroll
            for (int o = 0; o < 64; o++) h3[o] = fmaf(hv[u], wrow[o], h3[o]);
        }
    }
    float accv = b4[0];
#pragma unroll
    for (int o = 0; o < 64; o++) accv = fmaf(fmaxf(h3[o], 0.f), sW4[o], accv);
    out[s] = accv;
}

// ---------------------------------------------------------------------------
extern "C" void kernel_launch(void* const* d_in, const int* in_sizes, int n_in,
                              void* d_out, int out_size) {
    const float* x  = (const float*)d_in[0];
    const float* W1 = (const float*)d_in[1];
    const float* b1 = (const float*)d_in[2];
    const float* W2 = (const float*)d_in[3];
    const float* b2 = (const float*)d_in[4];
    const float* W3 = (const float*)d_in[5];
    const float* b3 = (const float*)d_in[6];
    const float* W4 = (const float*)d_in[7];
    const float* b4 = (const float*)d_in[8];
    float* out = (float*)d_out;

    float *feats, *h1, *h2;
    cudaGetSymbolAddress((void**)&feats, g_feats);
    cudaGetSymbolAddress((void**)&h1, g_h1);
    cudaGetSymbolAddress((void**)&h2, g_h2);

    // features
    feat_kernel<<<BATCH / 8, 256>>>(x);
    // singular values
    svd_kernel<<<BATCH / 128, 128>>>();
    // layer 1: [B,1808] @ [1808,256] + b1, relu
    {
        dim3 grid(256 / 128, BATCH / 128);
        sgemm_bias_relu<<<grid, 256>>>(BATCH, 256, FEAT, feats, W1, b1, h1, 1);
    }
    // layer 2: [B,256] @ [256,128] + b2, relu
    {
        dim3 grid(128 / 128, BATCH / 128);
        sgemm_bias_relu<<<grid, 256>>>(BATCH, 128, 256, h1, W2, b2, h2, 1);
    }
    // layers 3+4 fused
    tail_kernel<<<BATCH / 256, 256>>>(W3, b3, W4, b4, out);
}

// round 2
// speedup vs baseline: 1.3422x; 1.3422x over previous
#include <cuda_runtime.h>
#include <math.h>

#define BATCH 65536
#define FEAT  1808

// Scratch (static device globals; no allocation in kernel_launch)
__device__ float g_feats[(size_t)BATCH * FEAT];   // [B, 1808]
__device__ float g_h1[(size_t)BATCH * 256];       // [B, 256]
__device__ float g_h2[(size_t)BATCH * 128];       // [B, 128]

// ---------------------------------------------------------------------------
// Kernel 1: features (x copy, gram_cols 32x32, gram_rows 16x16), warp/sample
// ---------------------------------------------------------------------------
__global__ __launch_bounds__(256) void feat_kernel(const float* __restrict__ x) {
    int gw = (blockIdx.x * blockDim.x + threadIdx.x) >> 5;  // sample id
    int lane = threadIdx.x & 31;
    if (gw >= BATCH) return;
    const float* xr = x + (size_t)gw * 512;
    float* fr = g_feats + (size_t)gw * FEAT;

    // lane holds column `lane` of P: c[k] = P[k][lane], coalesced loads
    float c[16];
#pragma unroll
    for (int k = 0; k < 16; k++) c[k] = xr[k * 32 + lane];

    // copy x into feats[0:512)
#pragma unroll
    for (int k = 0; k < 16; k++) fr[k * 32 + lane] = c[k];

    // gram_cols[i][j] = sum_k P[k][i]*P[k][j]; j = lane
#pragma unroll
    for (int i = 0; i < 32; i++) {
        float acc = 0.f;
#pragma unroll
        for (int k = 0; k < 16; k++)
            acc = fmaf(__shfl_sync(0xffffffffu, c[k], i), c[k], acc);
        fr[512 + i * 32 + lane] = acc;
    }

    // gram_rows[i][j] = sum_c P[i][c]*P[j][c] = warp-reduce over lanes of c[i]*c[j]
    float outv[8];
#pragma unroll
    for (int r = 0; r < 8; r++) outv[r] = 0.f;
#pragma unroll
    for (int i = 0; i < 16; i++) {
#pragma unroll
        for (int j = i; j < 16; j++) {
            float v = c[i] * c[j];
            v += __shfl_xor_sync(0xffffffffu, v, 16);
            v += __shfl_xor_sync(0xffffffffu, v, 8);
            v += __shfl_xor_sync(0xffffffffu, v, 4);
            v += __shfl_xor_sync(0xffffffffu, v, 2);
            v += __shfl_xor_sync(0xffffffffu, v, 1);
            int p1 = i * 16 + j;
            if (lane == (p1 & 31)) outv[p1 >> 5] = v;
            if (i != j) {
                int p2 = j * 16 + i;
                if (lane == (p2 & 31)) outv[p2 >> 5] = v;
            }
        }
    }
#pragma unroll
    for (int r = 0; r < 8; r++) fr[1536 + r * 32 + lane] = outv[r];
}

// ---------------------------------------------------------------------------
// Kernel 2: singular values via per-thread cyclic Jacobi on 16x16 Gram.
// Branchless rotations (uniform control flow), 5 sweeps.
// ---------------------------------------------------------------------------
__device__ __forceinline__ constexpr int SIDX(int i, int j) {
    // requires i <= j
    return i * 16 - i * (i - 1) / 2 + (j - i);
}

__global__ __launch_bounds__(128) void svd_kernel() {
    int s = blockIdx.x * blockDim.x + threadIdx.x;
    if (s >= BATCH) return;
    float* fr = g_feats + (size_t)s * FEAT;

    float a[136];
#pragma unroll
    for (int i = 0; i < 16; i++)
#pragma unroll
        for (int j = i; j < 16; j++)
            a[SIDX(i, j)] = fr[1536 + i * 16 + j];

#pragma unroll 1
    for (int sw = 0; sw < 5; sw++) {
#pragma unroll
        for (int p = 0; p < 15; p++) {
#pragma unroll
            for (int q = p + 1; q < 16; q++) {
                float apq = a[SIDX(p, q)];
                float app = a[SIDX(p, p)];
                float aqq = a[SIDX(q, q)];
                float theta = __fdividef(0.5f * (aqq - app), apq);
                float t = copysignf(1.0f, theta) /
                          (fabsf(theta) + sqrtf(fmaf(theta, theta, 1.0f)));
                // guard: apq == 0 -> theta is inf/NaN -> force identity rotation
                t = (apq == 0.0f) ? 0.0f : t;
                float cth = rsqrtf(fmaf(t, t, 1.0f));
                float sth = t * cth;
                a[SIDX(p, p)] = app - t * apq;
                a[SIDX(q, q)] = aqq + t * apq;
                a[SIDX(p, q)] = 0.f;
#pragma unroll
                for (int i = 0; i < 16; i++) {
                    if (i != p && i != q) {
                        float aip = (i < p) ? a[SIDX(i, p)] : a[SIDX(p, i)];
                        float aiq = (i < q) ? a[SIDX(i, q)] : a[SIDX(q, i)];
                        float n1 = cth * aip - sth * aiq;
                        float n2 = sth * aip + cth * aiq;
                        if (i < p) a[SIDX(i, p)] = n1; else a[SIDX(p, i)] = n1;
                        if (i < q) a[SIDX(i, q)] = n2; else a[SIDX(q, i)] = n2;
                    }
                }
            }
        }
    }

    float sv[16];
#pragma unroll
    for (int i = 0; i < 16; i++) sv[i] = sqrtf(fmaxf(a[SIDX(i, i)], 0.f));

    // sort descending: unrolled bubble network (static indices -> registers)
#pragma unroll
    for (int i = 0; i < 15; i++)
#pragma unroll
        for (int j = 0; j < 15 - i; j++) {
            float hi = fmaxf(sv[j], sv[j + 1]);
            float lo = fminf(sv[j], sv[j + 1]);
            sv[j] = hi;
            sv[j + 1] = lo;
        }
#pragma unroll
    for (int i = 0; i < 16; i++) fr[1792 + i] = sv[i];
}

// ---------------------------------------------------------------------------
// SGEMM: C[M,N] = relu?(A[M,K] @ B[K,N] + bias), 128x128 tile, 8x8/thread,
// double-buffered shared memory, one sync per K-tile.
// Requires: M%128==0, N%128==0, K%16==0
// ---------------------------------------------------------------------------
__global__ __launch_bounds__(256) void sgemm_bias_relu(
    int M, int N, int K,
    const float* __restrict__ A,
    const float* __restrict__ Bw,
    const float* __restrict__ bias,
    float* __restrict__ C,
    int do_relu)
{
    const int BK = 16;
    __shared__ float As[2][BK][128];
    __shared__ float Bs[2][BK][128];
    int tid = threadIdx.x;
    int bx = blockIdx.x, by = blockIdx.y;
    int tcol = tid & 15, trow = tid >> 4;

    float acc[8][8];
#pragma unroll
    for (int i = 0; i < 8; i++)
#pragma unroll
        for (int j = 0; j < 8; j++) acc[i][j] = 0.f;

    const float* Ab = A + (size_t)by * 128 * K;
    const float* Bb = Bw + bx * 128;

    int arow = tid >> 2, acol = (tid & 3) << 2;
    int brow = tid >> 5, bcol = (tid & 31) << 2;

    // preload tile 0
    float4 av0 = *(const float4*)(Ab + (size_t)arow * K + acol);
    float4 av1 = *(const float4*)(Ab + (size_t)(arow + 64) * K + acol);
    float4 bv0 = *(const float4*)(Bb + (size_t)brow * N + bcol);
    float4 bv1 = *(const float4*)(Bb + (size_t)(brow + 8) * N + bcol);
    As[0][acol + 0][arow] = av0.x; As[0][acol + 1][arow] = av0.y;
    As[0][acol + 2][arow] = av0.z; As[0][acol + 3][arow] = av0.w;
    As[0][acol + 0][arow + 64] = av1.x; As[0][acol + 1][arow + 64] = av1.y;
    As[0][acol + 2][arow + 64] = av1.z; As[0][acol + 3][arow + 64] = av1.w;
    *(float4*)&Bs[0][brow][bcol] = bv0;
    *(float4*)&Bs[0][brow + 8][bcol] = bv1;
    __syncthreads();

    int buf = 0;
    for (int k0 = 0; k0 < K; k0 += BK) {
        bool has_next = (k0 + BK) < K;
        // prefetch next tile into registers (LDGs in flight during compute)
        if (has_next) {
            int kn = k0 + BK;
            av0 = *(const float4*)(Ab + (size_t)arow * K + kn + acol);
            av1 = *(const float4*)(Ab + (size_t)(arow + 64) * K + kn + acol);
            bv0 = *(const float4*)(Bb + (size_t)(kn + brow) * N + bcol);
            bv1 = *(const float4*)(Bb + (size_t)(kn + brow + 8) * N + bcol);
        }

#pragma unroll
        for (int k = 0; k < BK; k++) {
            float ra[8], rb[8];
            *(float4*)(ra)     = *(const float4*)&As[buf][k][trow * 8];
            *(float4*)(ra + 4) = *(const float4*)&As[buf][k][trow * 8 + 4];
            *(float4*)(rb)     = *(const float4*)&Bs[buf][k][tcol * 8];
            *(float4*)(rb + 4) = *(const float4*)&Bs[buf][k][tcol * 8 + 4];
#pragma unroll
            for (int i = 0; i < 8; i++)
#pragma unroll
                for (int j = 0; j < 8; j++)
                    acc[i][j] = fmaf(ra[i], rb[j], acc[i][j]);
        }

        if (has_next) {
            int nb = buf ^ 1;
            As[nb][acol + 0][arow] = av0.x; As[nb][acol + 1][arow] = av0.y;
            As[nb][acol + 2][arow] = av0.z; As[nb][acol + 3][arow] = av0.w;
            As[nb][acol + 0][arow + 64] = av1.x; As[nb][acol + 1][arow + 64] = av1.y;
            As[nb][acol + 2][arow + 64] = av1.z; As[nb][acol + 3][arow + 64] = av1.w;
            *(float4*)&Bs[nb][brow][bcol] = bv0;
            *(float4*)&Bs[nb][brow + 8][bcol] = bv1;
            __syncthreads();
            buf = nb;
        }
    }

    // epilogue: bias + relu, float4 stores
#pragma unroll
    for (int i = 0; i < 8; i++) {
        size_t row = (size_t)by * 128 + trow * 8 + i;
#pragma unroll
        for (int jv = 0; jv < 2; jv++) {
            int col = bx * 128 + tcol * 8 + jv * 4;
            float4 v;
            v.x = acc[i][jv * 4 + 0] + bias[col + 0];
            v.y = acc[i][jv * 4 + 1] + bias[col + 1];
            v.z = acc[i][jv * 4 + 2] + bias[col + 2];
            v.w = acc[i][jv * 4 + 3] + bias[col + 3];
            if (do_relu) {
                v.x = fmaxf(v.x, 0.f); v.y = fmaxf(v.y, 0.f);
                v.z = fmaxf(v.z, 0.f); v.w = fmaxf(v.w, 0.f);
            }
            *(float4*)(C + row * N + col) = v;
        }
    }
}

// ---------------------------------------------------------------------------
// Kernel 4: fused layers 3+4: out = relu(h2 @ W3 + b3) @ W4 + b4
// ---------------------------------------------------------------------------
__global__ __launch_bounds__(256) void tail_kernel(
    const float* __restrict__ W3, const float* __restrict__ b3,
    const float* __restrict__ W4, const float* __restrict__ b4,
    float* __restrict__ out)
{
    __shared__ float sW3[128 * 64];
    __shared__ float sb3[64];
    __shared__ float sW4[64];
    int tid = threadIdx.x;
    for (int i = tid; i < 128 * 64; i += 256) sW3[i] = W3[i];
    if (tid < 64) { sb3[tid] = b3[tid]; sW4[tid] = W4[tid]; }
    __syncthreads();

    int s = blockIdx.x * 256 + tid;
    if (s >= BATCH) return;
    const float4* h2r = (const float4*)(g_h2 + (size_t)s * 128);

    float h3[64];
#pragma unroll
    for (int o = 0; o < 64; o++) h3[o] = sb3[o];

    for (int k4 = 0; k4 < 32; k4++) {
        float4 v = h2r[k4];
        float hv[4] = {v.x, v.y, v.z, v.w};
#pragma unroll
        for (int u = 0; u < 4; u++) {
            const float* wrow = &sW3[(k4 * 4 + u) * 64];
#pragma unroll
            for (int o = 0; o < 64; o++) h3[o] = fmaf(hv[u], wrow[o], h3[o]);
        }
    }
    float accv = b4[0];
#pragma unroll
    for (int o = 0; o < 64; o++) accv = fmaf(fmaxf(h3[o], 0.f), sW4[o], accv);
    out[s] = accv;
}

// ---------------------------------------------------------------------------
extern "C" void kernel_launch(void* const* d_in, const int* in_sizes, int n_in,
                              void* d_out, int out_size) {
    const float* x  = (const float*)d_in[0];
    const float* W1 = (const float*)d_in[1];
    const float* b1 = (const float*)d_in[2];
    const float* W2 = (const float*)d_in[3];
    const float* b2 = (const float*)d_in[4];
    const float* W3 = (const float*)d_in[5];
    const float* b3 = (const float*)d_in[6];
    const float* W4 = (const float*)d_in[7];
    const float* b4 = (const float*)d_in[8];
    float* out = (float*)d_out;

    float *feats, *h1, *h2;
    cudaGetSymbolAddress((void**)&feats, g_feats);
    cudaGetSymbolAddress((void**)&h1, g_h1);
    cudaGetSymbolAddress((void**)&h2, g_h2);

    // features
    feat_kernel<<<BATCH / 8, 256>>>(x);
    // singular values
    svd_kernel<<<BATCH / 128, 128>>>();
    // layer 1: [B,1808] @ [1808,256] + b1, relu
    {
        dim3 grid(256 / 128, BATCH / 128);
        sgemm_bias_relu<<<grid, 256>>>(BATCH, 256, FEAT, feats, W1, b1, h1, 1);
    }
    // layer 2: [B,256] @ [256,128] + b2, relu
    {
        dim3 grid(128 / 128, BATCH / 128);
        sgemm_bias_relu<<<grid, 256>>>(BATCH, 128, 256, h1, W2, b2, h2, 1);
    }
    // layers 3+4 fused
    tail_kernel<<<BATCH / 256, 256>>>(W3, b3, W4, b4, out);
}

// round 4
// speedup vs baseline: 2.1225x; 1.5814x over previous
#include <cuda_runtime.h>
#include <math.h>
#include <stdint.h>

#define BATCH 65536
#define FEAT  1808

// Scratch (static device globals; no allocation in kernel_launch)
__device__ float g_feats[(size_t)BATCH * FEAT];   // [B, 1808]
__device__ float g_h1[(size_t)BATCH * 256];       // [B, 256]
__device__ float g_h2[(size_t)BATCH * 128];       // [B, 128]

// ---------------------------------------------------------------------------
// Kernel 1: features (x copy, gram_cols 32x32, gram_rows 16x16), warp/sample
// ---------------------------------------------------------------------------
__global__ __launch_bounds__(256) void feat_kernel(const float* __restrict__ x) {
    int gw = (blockIdx.x * blockDim.x + threadIdx.x) >> 5;  // sample id
    int lane = threadIdx.x & 31;
    if (gw >= BATCH) return;
    const float* xr = x + (size_t)gw * 512;
    float* fr = g_feats + (size_t)gw * FEAT;

    float c[16];
#pragma unroll
    for (int k = 0; k < 16; k++) c[k] = xr[k * 32 + lane];

#pragma unroll
    for (int k = 0; k < 16; k++) fr[k * 32 + lane] = c[k];

    // gram_cols[i][j] = sum_k P[k][i]*P[k][j]; j = lane
#pragma unroll
    for (int i = 0; i < 32; i++) {
        float acc = 0.f;
#pragma unroll
        for (int k = 0; k < 16; k++)
            acc = fmaf(__shfl_sync(0xffffffffu, c[k], i), c[k], acc);
        fr[512 + i * 32 + lane] = acc;
    }

    // gram_rows[i][j] = warp-reduce over lanes of c[i]*c[j]
    float outv[8];
#pragma unroll
    for (int r = 0; r < 8; r++) outv[r] = 0.f;
#pragma unroll
    for (int i = 0; i < 16; i++) {
#pragma unroll
        for (int j = i; j < 16; j++) {
            float v = c[i] * c[j];
            v += __shfl_xor_sync(0xffffffffu, v, 16);
            v += __shfl_xor_sync(0xffffffffu, v, 8);
            v += __shfl_xor_sync(0xffffffffu, v, 4);
            v += __shfl_xor_sync(0xffffffffu, v, 2);
            v += __shfl_xor_sync(0xffffffffu, v, 1);
            int p1 = i * 16 + j;
            if (lane == (p1 & 31)) outv[p1 >> 5] = v;
            if (i != j) {
                int p2 = j * 16 + i;
                if (lane == (p2 & 31)) outv[p2 >> 5] = v;
            }
        }
    }
#pragma unroll
    for (int r = 0; r < 8; r++) fr[1536 + r * 32 + lane] = outv[r];
}

// ---------------------------------------------------------------------------
// Kernel 2: singular values via cyclic Jacobi on 16x16 Gram, matrix held in
// SHARED memory (per-thread row, stride 137 -> conflict-free), dynamic loops.
// ---------------------------------------------------------------------------
__device__ __forceinline__ constexpr int SIDX(int i, int j) {
    return i * 16 - i * (i - 1) / 2 + (j - i);   // i <= j
}
__device__ __forceinline__ int ROFF(int i) {     // SIDX(i,j) = ROFF(i)+j for j>=i
    return i * 16 - i * (i - 1) / 2 - i;
}

__global__ __launch_bounds__(64) void svd_kernel() {
    __shared__ float sa[64 * 137];
    int t = threadIdx.x;
    size_t s = (size_t)blockIdx.x * 64 + t;
    float* fr = g_feats + s * FEAT;
    float* m = sa + t * 137;

#pragma unroll
    for (int i = 0; i < 16; i++)
#pragma unroll
        for (int j = i; j < 16; j++)
            m[SIDX(i, j)] = fr[1536 + i * 16 + j];

#pragma unroll 1
    for (int sw = 0; sw < 5; sw++) {
#pragma unroll 1
        for (int p = 0; p < 15; p++) {
            int roffp = ROFF(p);
#pragma unroll 1
            for (int q = p + 1; q < 16; q++) {
                int roffq = ROFF(q);
                float apq = m[roffp + q];
                float app = m[roffp + p];
                float aqq = m[roffq + q];
                float theta = __fdividef(0.5f * (aqq - app), apq);
                float tt = copysignf(1.0f, theta) /
                           (fabsf(theta) + sqrtf(fmaf(theta, theta, 1.0f)));
                tt = (apq == 0.0f) ? 0.0f : tt;   // guard inf/NaN
                float cth = rsqrtf(fmaf(tt, tt, 1.0f));
                float sth = tt * cth;
                m[roffp + p] = app - tt * apq;
                m[roffq + q] = aqq + tt * apq;
                m[roffp + q] = 0.f;
#pragma unroll
                for (int i = 0; i < 16; i++) {
                    int ip = (i < p) ? (ROFF(i) + p) : (roffp + i);
                    int iq = (i < q) ? (ROFF(i) + q) : (roffq + i);
                    float aip = m[ip], aiq = m[iq];
                    float n1 = cth * aip - sth * aiq;
                    float n2 = sth * aip + cth * aiq;
                    if (i != p && i != q) { m[ip] = n1; m[iq] = n2; }
                }
            }
        }
    }

    float sv[16];
#pragma unroll
    for (int i = 0; i < 16; i++) sv[i] = sqrtf(fmaxf(m[ROFF(i) + i], 0.f));  // diag = SIDX(i,i)

    // sort descending (register sorting network)
#pragma unroll
    for (int i = 0; i < 15; i++)
#pragma unroll
        for (int j = 0; j < 15 - i; j++) {
            float hi = fmaxf(sv[j], sv[j + 1]);
            float lo = fminf(sv[j], sv[j + 1]);
            sv[j] = hi;
            sv[j + 1] = lo;
        }
    float4* o = (float4*)(fr + 1792);
#pragma unroll
    for (int i = 0; i < 4; i++)
        o[i] = make_float4(sv[i * 4], sv[i * 4 + 1], sv[i * 4 + 2], sv[i * 4 + 3]);
}

// ---------------------------------------------------------------------------
// TF32 tensor-core GEMM: C = relu?(A[M,K] @ B[K,N] + bias)
// BM=128, BN=128, BK=16, 8 warps (2x4), each warp 64x32 via m16n8k8 mma.
// Smem in fragment-permuted layout -> conflict-free LDS.128/LDS.64.
// Requires M%128==0, N%128==0, K%16==0.
// ---------------------------------------------------------------------------
__device__ __forceinline__ uint32_t f2tf(float f) {
    uint32_t u;
    asm("cvt.rna.tf32.f32 %0, %1;" : "=r"(u) : "f"(f));
    return u;
}

__device__ __forceinline__ void mma_tf32(float* d, const uint32_t* a, const uint32_t* b) {
    asm volatile(
        "mma.sync.aligned.m16n8k8.row.col.f32.tf32.tf32.f32 "
        "{%0,%1,%2,%3}, {%4,%5,%6,%7}, {%8,%9}, {%0,%1,%2,%3};"
        : "+f"(d[0]), "+f"(d[1]), "+f"(d[2]), "+f"(d[3])
        : "r"(a[0]), "r"(a[1]), "r"(a[2]), "r"(a[3]), "r"(b[0]), "r"(b[1]));
}

__global__ __launch_bounds__(256) void gemm_tf32(
    int M, int N, int K,
    const float* __restrict__ A,
    const float* __restrict__ Bw,
    const float* __restrict__ bias,
    float* __restrict__ C,
    int do_relu)
{
    __shared__ uint32_t As[2][2048];   // [mtg(8)][ks(2)][lane(32)][r(4)]
    __shared__ uint32_t Bs[2][2048];   // [ntg(16)][ks(2)][lane(32)][r(2)]
    int tid = threadIdx.x;
    int bx = blockIdx.x, by = blockIdx.y;
    int warp = tid >> 5, lane = tid & 31;
    int wm = warp >> 2, wn = warp & 3;

    const float* Ab = A + (size_t)by * 128 * K;
    const float* Bb = Bw + bx * 128;

    // ---- loader index precompute ----
    int rowA = tid >> 1;             // 0..127
    int colA = (tid & 1) * 8;        // 0 or 8
    int mtA = rowA >> 4, mmA = rowA & 15, gA = mmA & 7, hiA = mmA >> 3;
    int ksA = colA >> 3;
    int abase = (((mtA * 2 + ksA) * 32) + gA * 4) * 4 + hiA;

    int rowB = tid >> 4;             // 0..15
    int colB = (tid & 15) * 8;       // 0..120
    int ksB = rowB >> 3, tB = rowB & 3, rB = (rowB >> 2) & 1;
    int nt0 = colB >> 3;
    int bbase = (((nt0 * 2 + ksB) * 32) + tB) * 2 + rB;

    float acc[4][4][4];
#pragma unroll
    for (int mt = 0; mt < 4; mt++)
#pragma unroll
        for (int nt = 0; nt < 4; nt++)
#pragma unroll
            for (int r = 0; r < 4; r++) acc[mt][nt][r] = 0.f;

    const float* Arow = Ab + (size_t)rowA * K + colA;
    const float* Brow = Bb + (size_t)rowB * N + colB;

    // preload tile 0
    float4 av0 = *(const float4*)(Arow);
    float4 av1 = *(const float4*)(Arow + 4);
    float4 bv0 = *(const float4*)(Brow);
    float4 bv1 = *(const float4*)(Brow + 4);
    {
        uint32_t* as = As[0];
        as[abase + 0]  = f2tf(av0.x); as[abase + 4]  = f2tf(av0.y);
        as[abase + 8]  = f2tf(av0.z); as[abase + 12] = f2tf(av0.w);
        as[abase + 2]  = f2tf(av1.x); as[abase + 6]  = f2tf(av1.y);
        as[abase + 10] = f2tf(av1.z); as[abase + 14] = f2tf(av1.w);
        uint32_t* bs = Bs[0];
        bs[bbase + 0]  = f2tf(bv0.x); bs[bbase + 8]  = f2tf(bv0.y);
        bs[bbase + 16] = f2tf(bv0.z); bs[bbase + 24] = f2tf(bv0.w);
        bs[bbase + 32] = f2tf(bv1.x); bs[bbase + 40] = f2tf(bv1.y);
        bs[bbase + 48] = f2tf(bv1.z); bs[bbase + 56] = f2tf(bv1.w);
    }
    __syncthreads();

    int buf = 0;
    for (int k0 = 0; k0 < K; k0 += 16) {
        bool has_next = (k0 + 16) < K;
        if (has_next) {
            av0 = *(const float4*)(Arow + k0 + 16);
            av1 = *(const float4*)(Arow + k0 + 20);
            bv0 = *(const float4*)(Brow + (size_t)(k0 + 16) * N);
            bv1 = *(const float4*)(Brow + (size_t)(k0 + 16) * N + 4);
        }

        const uint32_t* as = As[buf];
        const uint32_t* bs = Bs[buf];
#pragma unroll
        for (int ks = 0; ks < 2; ks++) {
            uint32_t af[4][4];
            uint32_t bf[4][2];
#pragma unroll
            for (int mt = 0; mt < 4; mt++)
                *(uint4*)af[mt] =
                    *(const uint4*)&as[(((wm * 4 + mt) * 2 + ks) * 32 + lane) * 4];
#pragma unroll
            for (int nt = 0; nt < 4; nt++) {
                const uint32_t* p = &bs[(((wn * 4 + nt) * 2 + ks) * 32 + lane) * 2];
                bf[nt][0] = p[0]; bf[nt][1] = p[1];
            }
#pragma unroll
            for (int mt = 0; mt < 4; mt++)
#pragma unroll
                for (int nt = 0; nt < 4; nt++)
                    mma_tf32(acc[mt][nt], af[mt], bf[nt]);
        }

        if (has_next) {
            int nb = buf ^ 1;
            uint32_t* asn = As[nb];
            asn[abase + 0]  = f2tf(av0.x); asn[abase + 4]  = f2tf(av0.y);
            asn[abase + 8]  = f2tf(av0.z); asn[abase + 12] = f2tf(av0.w);
            asn[abase + 2]  = f2tf(av1.x); asn[abase + 6]  = f2tf(av1.y);
            asn[abase + 10] = f2tf(av1.z); asn[abase + 14] = f2tf(av1.w);
            uint32_t* bsn = Bs[nb];
            bsn[bbase + 0]  = f2tf(bv0.x); bsn[bbase + 8]  = f2tf(bv0.y);
            bsn[bbase + 16] = f2tf(bv0.z); bsn[bbase + 24] = f2tf(bv0.w);
            bsn[bbase + 32] = f2tf(bv1.x); bsn[bbase + 40] = f2tf(bv1.y);
            bsn[bbase + 48] = f2tf(bv1.z); bsn[bbase + 56] = f2tf(bv1.w);
            __syncthreads();
            buf = nb;
        }
    }

    // epilogue
    int gc = lane >> 2, tc = lane & 3;
#pragma unroll
    for (int mt = 0; mt < 4; mt++) {
        int m0 = by * 128 + wm * 64 + mt * 16 + gc;
#pragma unroll
        for (int nt = 0; nt < 4; nt++) {
            int n = bx * 128 + wn * 32 + nt * 8 + tc * 2;
            float b0v = bias[n], b1v = bias[n + 1];
            float v0 = acc[mt][nt][0] + b0v;
            float v1 = acc[mt][nt][1] + b1v;
            float v2 = acc[mt][nt][2] + b0v;
            float v3 = acc[mt][nt][3] + b1v;
            if (do_relu) {
                v0 = fmaxf(v0, 0.f); v1 = fmaxf(v1, 0.f);
                v2 = fmaxf(v2, 0.f); v3 = fmaxf(v3, 0.f);
            }
            *(float2*)(C + (size_t)m0 * N + n)       = make_float2(v0, v1);
            *(float2*)(C + (size_t)(m0 + 8) * N + n) = make_float2(v2, v3);
        }
    }
}

// ---------------------------------------------------------------------------
// Kernel 4: fused layers 3+4: out = relu(h2 @ W3 + b3) @ W4 + b4
// ---------------------------------------------------------------------------
__global__ __launch_bounds__(256) void tail_kernel(
    const float* __restrict__ W3, const float* __restrict__ b3,
    const float* __restrict__ W4, const float* __restrict__ b4,
    float* __restrict__ out)
{
    __shared__ float sW3[128 * 64];
    __shared__ float sb3[64];
    __shared__ float sW4[64];
    int tid = threadIdx.x;
    for (int i = tid; i < 128 * 64; i += 256) sW3[i] = W3[i];
    if (tid < 64) { sb3[tid] = b3[tid]; sW4[tid] = W4[tid]; }
    __syncthreads();

    int s = blockIdx.x * 256 + tid;
    if (s >= BATCH) return;
    const float4* h2r = (const float4*)(g_h2 + (size_t)s * 128);

    float h3[64];
#pragma unroll
    for (int o = 0; o < 64; o++) h3[o] = sb3[o];

    for (int k4 = 0; k4 < 32; k4++) {
        float4 v = h2r[k4];
        float hv[4] = {v.x, v.y, v.z, v.w};
#pragma unroll
        for (int u = 0; u < 4; u++) {
            const float* wrow = &sW3[(k4 * 4 + u) * 64];
#pragma unroll
            for (int o = 0; o < 64; o++) h3[o] = fmaf(hv[u], wrow[o], h3[o]);
        }
    }
    float accv = b4[0];
#pragma unroll
    for (int o = 0; o < 64; o++) accv = fmaf(fmaxf(h3[o], 0.f), sW4[o], accv);
    out[s] = accv;
}

// ---------------------------------------------------------------------------
extern "C" void kernel_launch(void* const* d_in, const int* in_sizes, int n_in,
                              void* d_out, int out_size) {
    const float* x  = (const float*)d_in[0];
    const float* W1 = (const float*)d_in[1];
    const float* b1 = (const float*)d_in[2];
    const float* W2 = (const float*)d_in[3];
    const float* b2 = (const float*)d_in[4];
    const float* W3 = (const float*)d_in[5];
    const float* b3 = (const float*)d_in[6];
    const float* W4 = (const float*)d_in[7];
    const float* b4 = (const float*)d_in[8];
    float* out = (float*)d_out;

    float *feats, *h1, *h2;
    cudaGetSymbolAddress((void**)&feats, g_feats);
    cudaGetSymbolAddress((void**)&h1, g_h1);
    cudaGetSymbolAddress((void**)&h2, g_h2);

    feat_kernel<<<BATCH / 8, 256>>>(x);
    svd_kernel<<<BATCH / 64, 64>>>();
    // layer 1: [B,1808] @ [1808,256] + b1, relu (tf32 tensor cores)
    {
        dim3 grid(256 / 128, BATCH / 128);
        gemm_tf32<<<grid, 256>>>(BATCH, 256, FEAT, feats, W1, b1, h1, 1);
    }
    // layer 2: [B,256] @ [256,128] + b2, relu
    {
        dim3 grid(128 / 128, BATCH / 128);
        gemm_tf32<<<grid, 256>>>(BATCH, 128, 256, h1, W2, b2, h2, 1);
    }
    tail_kernel<<<BATCH / 256, 256>>>(W3, b3, W4, b4, out);
}